// round 11
// baseline (speedup 1.0000x reference)
#include <cuda_runtime.h>

// ----------------------------------------------------------------------------
// SymplecticGyroceptron — R10 resubmit (prior bench was an infra failure:
// "GB300 container failed twice" — kernel never ran).
//
// R9 + tanh.approx.f16x2 (halve MUFU work).
//
// R4/R9 plateau diagnosis: identical 798us at 24 AND 32 warps/SM -> bound by
// a pipe not shown in the roofline summary = MUFU. tanh.approx.f32 at
// rt_SMSP~8 gives a ~665us issue floor; we sit on it. Fix: evaluate both
// points' tanh in ONE tanh.approx.f16x2 (pack via cvt.rn.f16x2.f32, unpack
// via cvt.f32.f16). MUFU count halves; +4 alu-class ops ride the idle (1.3%)
// alu pipe. All other math stays fp32 (R9-exact).
//
// Datapath per neuron per 2 pts:
//   LDS.128 (wx,wy,b,wwx) + LDS.32 (wwy)
//   4 scalar FMA (pre), 1 cvt-pack, 1 tanh.f16x2, 1 mov-split, 2 cvt-f32,
//   pack -> FFMA2 (t^2-1) -> 2 FFMA2 acc.
// wwx = -eps*wout*wx, wwy = -eps*wout*wy (negated: t^2-1 trick).
// ----------------------------------------------------------------------------

#define NEUR 64
#define NLAYERS 16   // 0..7 = psi (eps=1), 8..15 = ni (eps=0.01)

typedef unsigned long long u64;

__device__ float4 g_packedA[NLAYERS * NEUR];
__device__ float  g_packedB[NLAYERS * NEUR];
__device__ float2 g_eta[NLAYERS];
__device__ float2 g_cs;

__device__ __forceinline__ u64 pack2(float lo, float hi) {
    u64 d; asm("mov.b64 %0, {%1, %2};" : "=l"(d) : "f"(lo), "f"(hi)); return d;
}
__device__ __forceinline__ void unpack2(u64 d, float& lo, float& hi) {
    asm("mov.b64 {%0, %1}, %2;" : "=f"(lo), "=f"(hi) : "l"(d));
}
__device__ __forceinline__ u64 ffma2(u64 a, u64 b, u64 c) {
    u64 d; asm("fma.rn.f32x2 %0, %1, %2, %3;" : "=l"(d) : "l"(a), "l"(b), "l"(c));
    return d;
}

// Both tanh evaluations in one MUFU op via f16x2. Returns fp32 (tA, tB).
__device__ __forceinline__ void tanh2_f16(float pA, float pB,
                                          float& tA, float& tB)
{
    unsigned int ph, th;
    unsigned short lo, hi;
    // pack: first fp32 operand -> upper half, second -> lower half
    asm("cvt.rn.f16x2.f32 %0, %1, %2;" : "=r"(ph) : "f"(pB), "f"(pA));
    asm("tanh.approx.f16x2 %0, %1;" : "=r"(th) : "r"(ph));
    asm("mov.b32 {%0, %1}, %2;" : "=h"(lo), "=h"(hi) : "r"(th));
    asm("cvt.f32.f16 %0, %1;" : "=f"(tA) : "h"(lo));
    asm("cvt.f32.f16 %0, %1;" : "=f"(tB) : "h"(hi));
}

__global__ void prep_kernel(const float* __restrict__ theta0,
                            const float* __restrict__ psi_Win,
                            const float* __restrict__ psi_Wout,
                            const float* __restrict__ psi_b,
                            const float* __restrict__ psi_eta,
                            const float* __restrict__ ni_Win,
                            const float* __restrict__ ni_Wout,
                            const float* __restrict__ ni_b,
                            const float* __restrict__ ni_eta)
{
    int t = threadIdx.x;
    if (t < NLAYERS * NEUR) {
        int l = t >> 6;
        int j = t & 63;
        const float *Win, *Wout, *b;
        float eps;
        int i;
        if (l < 8) { i = l;     Win = psi_Win; Wout = psi_Wout; b = psi_b; eps = 1.0f;  }
        else       { i = l - 8; Win = ni_Win;  Wout = ni_Wout;  b = ni_b;  eps = 0.01f; }
        float w0 = Win[i * 128 + j];        // W_in[i][0][j]
        float w1 = Win[i * 128 + 64 + j];   // W_in[i][1][j]
        float bb = b[i * 64 + j];           // b_in[i][0][j]
        float wo = -Wout[i * 64 + j] * eps; // NEGATED eps*W_out (t^2-1 trick)
        g_packedA[t] = make_float4(w0, w1, bb, wo * w0);
        g_packedB[t] = wo * w1;
    }
    if (t < NLAYERS) {
        const float* e = (t < 8) ? (psi_eta + t * 2) : (ni_eta + (t - 8) * 2);
        g_eta[t] = make_float2(e[0], e[1]);
    }
    if (t == 0) {
        float th = theta0[0];
        g_cs = make_float2(cosf(th), sinf(th));
    }
}

// grad_V for two points simultaneously. Accumulators packed (A in lo, B in hi).
__device__ __forceinline__ void grad2x2(const float4* __restrict__ swA,
                                        const float*  __restrict__ swB,
                                        float yA0, float yA1,
                                        float yB0, float yB1,
                                        float& gA0, float& gA1,
                                        float& gB0, float& gB1)
{
    const u64 NEG1 = pack2(-1.0f, -1.0f);
    u64 acc0a = 0ull, acc1a = 0ull, acc0b = 0ull, acc1b = 0ull;
#pragma unroll 4
    for (int j = 0; j < NEUR; j += 2) {
        {
            float4 w  = swA[j];
            float  wy = swB[j];
            float pA = fmaf(yA0, w.x, fmaf(yA1, w.y, w.z));
            float pB = fmaf(yB0, w.x, fmaf(yB1, w.y, w.z));
            float tA, tB;
            tanh2_f16(pA, pB, tA, tB);
            u64 tp  = pack2(tA, tB);
            u64 t2m = ffma2(tp, tp, NEG1);        // t^2 - 1
            acc0a = ffma2(t2m, pack2(w.w, w.w), acc0a);
            acc1a = ffma2(t2m, pack2(wy,  wy ), acc1a);
        }
        {
            float4 w  = swA[j + 1];
            float  wy = swB[j + 1];
            float pA = fmaf(yA0, w.x, fmaf(yA1, w.y, w.z));
            float pB = fmaf(yB0, w.x, fmaf(yB1, w.y, w.z));
            float tA, tB;
            tanh2_f16(pA, pB, tA, tB);
            u64 tp  = pack2(tA, tB);
            u64 t2m = ffma2(tp, tp, NEG1);
            acc0b = ffma2(t2m, pack2(w.w, w.w), acc0b);
            acc1b = ffma2(t2m, pack2(wy,  wy ), acc1b);
        }
    }
    float a0A, a0B, b0A, b0B, a1A, a1B, b1A, b1B;
    unpack2(acc0a, a0A, a0B); unpack2(acc0b, b0A, b0B);
    unpack2(acc1a, a1A, a1B); unpack2(acc1b, b1A, b1B);
    gA0 = a0A + b0A;  gB0 = a0B + b0B;
    gA1 = a1A + b1A;  gB1 = a1B + b1B;
}

__global__ void __launch_bounds__(256, 4)
gyro_kernel(const float4* __restrict__ rin, float4* __restrict__ out,
            int B, int half)
{
    __shared__ float4 swA[NLAYERS * NEUR];
    __shared__ float  swB[NLAYERS * NEUR];
    __shared__ float2 seta[NLAYERS];
    __shared__ float2 scs;

    for (int i = threadIdx.x; i < NLAYERS * NEUR; i += blockDim.x) {
        swA[i] = g_packedA[i];
        swB[i] = g_packedB[i];
    }
    if (threadIdx.x < NLAYERS) seta[threadIdx.x] = g_eta[threadIdx.x];
    if (threadIdx.x == 0)      scs = g_cs;
    __syncthreads();

    int idx = blockIdx.x * blockDim.x + threadIdx.x;
    if (idx >= half) return;
    int idx2 = idx + half;
    bool hasB = (idx2 < B);
    int i2 = hasB ? idx2 : idx;

    float4 zA = rin[idx];
    float4 zB = rin[i2];
    float xA0 = zA.x, xA1 = zA.y, yA0 = zA.z, yA1 = zA.w;
    float xB0 = zB.x, xB1 = zB.y, yB0 = zB.z, yB1 = zB.w;

    // ---- inverse psi layers, l = 7 .. 0 ----
    for (int l = 7; l >= 0; --l) {
        float e0 = seta[l].x, e1 = seta[l].y;
        const float4* wA = &swA[l * NEUR];
        const float*  wB = &swB[l * NEUR];
#pragma unroll 1
        for (int k = 0; k < 4; ++k) {
            float ynA0 = xA0 - e0, ynA1 = xA1 - e1;
            float ynB0 = xB0 - e0, ynB1 = xB1 - e1;
            float gA0, gA1, gB0, gB1;
            grad2x2(wA, wB, ynA0, ynA1, ynB0, ynB1, gA0, gA1, gB0, gB1);
            float nxA0 = gA0 - yA0, nxA1 = gA1 - yA1;
            float nxB0 = gB0 - yB0, nxB1 = gB1 - yB1;
            yA0 = ynA0; yA1 = ynA1; xA0 = nxA0; xA1 = nxA1;
            yB0 = ynB0; yB1 = ynB1; xB0 = nxB0; xB1 = nxB1;
        }
    }

    // ---- circle action ----
    {
        float c = scs.x, s = scs.y;
        float q1 = xA0, p1 = yA0;
        xA0 = fmaf(c, q1, s * p1);
        yA0 = fmaf(c, p1, -s * q1);
        q1 = xB0; p1 = yB0;
        xB0 = fmaf(c, q1, s * p1);
        yB0 = fmaf(c, p1, -s * q1);
    }

    // ---- forward layers: l = 0..7 psi, l = 8..15 ni ----
    for (int l = 0; l < NLAYERS; ++l) {
        float e0 = seta[l].x, e1 = seta[l].y;
        const float4* wA = &swA[l * NEUR];
        const float*  wB = &swB[l * NEUR];
#pragma unroll 1
        for (int k = 0; k < 4; ++k) {
            float gA0, gA1, gB0, gB1;
            grad2x2(wA, wB, yA0, yA1, yB0, yB1, gA0, gA1, gB0, gB1);
            float nxA0 = yA0 + e0, nxA1 = yA1 + e1;
            float nyA0 = gA0 - xA0, nyA1 = gA1 - xA1;
            float nxB0 = yB0 + e0, nxB1 = yB1 + e1;
            float nyB0 = gB0 - xB0, nyB1 = gB1 - xB1;
            xA0 = nxA0; xA1 = nxA1; yA0 = nyA0; yA1 = nyA1;
            xB0 = nxB0; xB1 = nxB1; yB0 = nyB0; yB1 = nyB1;
        }
    }

    out[idx] = make_float4(xA0, xA1, yA0, yA1);
    if (hasB)
        out[idx2] = make_float4(xB0, xB1, yB0, yB1);
}

extern "C" void kernel_launch(void* const* d_in, const int* in_sizes, int n_in,
                              void* d_out, int out_size)
{
    const float* r        = (const float*)d_in[0];
    const float* theta0   = (const float*)d_in[1];
    const float* psi_Win  = (const float*)d_in[2];
    const float* psi_Wout = (const float*)d_in[3];
    const float* psi_b    = (const float*)d_in[4];
    const float* psi_eta  = (const float*)d_in[5];
    const float* ni_Win   = (const float*)d_in[6];
    const float* ni_Wout  = (const float*)d_in[7];
    const float* ni_b     = (const float*)d_in[8];
    const float* ni_eta   = (const float*)d_in[9];

    int B = in_sizes[0] / 4;
    int half = (B + 1) / 2;

    prep_kernel<<<1, 1024>>>(theta0, psi_Win, psi_Wout, psi_b, psi_eta,
                             ni_Win, ni_Wout, ni_b, ni_eta);

    int threads = 256;
    int blocks = (half + threads - 1) / threads;
    gyro_kernel<<<blocks, threads>>>((const float4*)r, (float4*)d_out, B, half);
}

// round 12
// speedup vs baseline: 1.0111x; 1.0111x over previous
#include <cuda_runtime.h>
#include <cuda_fp16.h>

// ----------------------------------------------------------------------------
// SymplecticGyroceptron — R12: fp16x2 inner loop (pre-activation + tanh +
// derivative), fp32 accumulation. 2 points/thread, R9-proven geometry.
//
// Floor model (calibrated on R9/R11): per neuron per 2 points,
//   time >= max(f_fma * 83us, t_tanh * 333us, alu * 83us, L1)
// R9: f=7,t=2 -> 665 floor, 798 meas. R11: f=10,t=1 -> 831 floor, 866 meas.
// R12: f~5-7 (2 HFMA2 pre + 1 HFMA2 t2m + 2 cvt + 2 FFMA2 acc), t=1.
//
// Shared per neuron (16B, ONE LDS.128, serves 2 pts = 8B/pt):
//   .x = h2(wx, wy)   (fp16 input weights, lo=wx hi=wy)
//   .y = h2(b, b)     (fp16 bias, pre-duplicated)
//   .z = f32 wwx = -eps*wout*wx     (t^2-1 trick: negated)
//   .w = f32 wwy = -eps*wout*wy
// In-loop: PRMT 0x1010/0x3232 duplicates wx/wy into h2 pairs (alu pipe).
// Points packed lo=A hi=B throughout (same convention as R11, verified).
// ----------------------------------------------------------------------------

#define NEUR 64
#define NLAYERS 16   // 0..7 = psi (eps=1), 8..15 = ni (eps=0.01)

typedef unsigned long long u64;
typedef unsigned int u32;

__device__ uint4  g_w[NLAYERS * NEUR];
__device__ float2 g_eta[NLAYERS];
__device__ float2 g_cs;

__device__ __forceinline__ u64 pack2(float lo, float hi) {
    u64 d; asm("mov.b64 %0, {%1, %2};" : "=l"(d) : "f"(lo), "f"(hi)); return d;
}
__device__ __forceinline__ void unpack2(u64 d, float& lo, float& hi) {
    asm("mov.b64 {%0, %1}, %2;" : "=f"(lo), "=f"(hi) : "l"(d));
}
__device__ __forceinline__ u64 ffma2(u64 a, u64 b, u64 c) {
    u64 d; asm("fma.rn.f32x2 %0, %1, %2, %3;" : "=l"(d) : "l"(a), "l"(b), "l"(c));
    return d;
}
__device__ __forceinline__ u32 hfma2(u32 a, u32 b, u32 c) {
    u32 d; asm("fma.rn.f16x2 %0, %1, %2, %3;" : "=r"(d) : "r"(a), "r"(b), "r"(c));
    return d;
}
__device__ __forceinline__ u32 prmt(u32 a, u32 sel) {
    u32 d; asm("prmt.b32 %0, %1, 0, %2;" : "=r"(d) : "r"(a), "r"(sel));
    return d;
}

__global__ void prep_kernel(const float* __restrict__ theta0,
                            const float* __restrict__ psi_Win,
                            const float* __restrict__ psi_Wout,
                            const float* __restrict__ psi_b,
                            const float* __restrict__ psi_eta,
                            const float* __restrict__ ni_Win,
                            const float* __restrict__ ni_Wout,
                            const float* __restrict__ ni_b,
                            const float* __restrict__ ni_eta)
{
    int t = threadIdx.x;
    if (t < NLAYERS * NEUR) {
        int l = t >> 6;
        int j = t & 63;
        const float *Win, *Wout, *b;
        float eps;
        int i;
        if (l < 8) { i = l;     Win = psi_Win; Wout = psi_Wout; b = psi_b; eps = 1.0f;  }
        else       { i = l - 8; Win = ni_Win;  Wout = ni_Wout;  b = ni_b;  eps = 0.01f; }
        float w0 = Win[i * 128 + j];        // W_in[i][0][j]
        float w1 = Win[i * 128 + 64 + j];   // W_in[i][1][j]
        float bb = b[i * 64 + j];           // b_in[i][0][j]
        float wo = -Wout[i * 64 + j] * eps; // NEGATED eps*W_out (t^2-1 trick)

        u32 hx = (u32)__half_as_ushort(__float2half_rn(w0));
        u32 hy = (u32)__half_as_ushort(__float2half_rn(w1));
        u32 hb = (u32)__half_as_ushort(__float2half_rn(bb));
        uint4 w;
        w.x = (hy << 16) | hx;              // h2(wx, wy): lo=wx, hi=wy
        w.y = (hb << 16) | hb;              // h2(b, b)
        w.z = __float_as_uint(wo * w0);     // f32 wwx
        w.w = __float_as_uint(wo * w1);     // f32 wwy
        g_w[t] = w;
    }
    if (t < NLAYERS) {
        const float* e = (t < 8) ? (psi_eta + t * 2) : (ni_eta + (t - 8) * 2);
        g_eta[t] = make_float2(e[0], e[1]);
    }
    if (t == 0) {
        float th = theta0[0];
        g_cs = make_float2(cosf(th), sinf(th));
    }
}

// grad_V for two points (A=lo halves, B=hi halves). fp16 pre+tanh+deriv,
// fp32 accumulate.
__device__ __forceinline__ void grad2x2(const uint4* __restrict__ sw,
                                        float yA0, float yA1,
                                        float yB0, float yB1,
                                        float& gA0, float& gA1,
                                        float& gB0, float& gB1)
{
    const u32 NEG1H = 0xBC00BC00u;   // h2(-1, -1)
    u32 Y0h, Y1h;
    // pack: %1 -> hi half, %2 -> lo half  (lo=A, hi=B; verified in R11)
    asm("cvt.rn.f16x2.f32 %0, %1, %2;" : "=r"(Y0h) : "f"(yB0), "f"(yA0));
    asm("cvt.rn.f16x2.f32 %0, %1, %2;" : "=r"(Y1h) : "f"(yB1), "f"(yA1));

    u64 acc0a = 0ull, acc1a = 0ull, acc0b = 0ull, acc1b = 0ull;
#pragma unroll 4
    for (int j = 0; j < NEUR; j += 2) {
        {
            uint4 w = sw[j];
            u32 wxx = prmt(w.x, 0x1010u);                 // h2(wx, wx)
            u32 wyy = prmt(w.x, 0x3232u);                 // h2(wy, wy)
            u32 p = hfma2(Y0h, wxx, hfma2(Y1h, wyy, w.y));
            u32 th; asm("tanh.approx.f16x2 %0, %1;" : "=r"(th) : "r"(p));
            u32 m = hfma2(th, th, NEG1H);                 // t^2 - 1 (fp16)
            unsigned short ml, mh;
            asm("mov.b32 {%0, %1}, %2;" : "=h"(ml), "=h"(mh) : "r"(m));
            float mA, mB;
            asm("cvt.f32.f16 %0, %1;" : "=f"(mA) : "h"(ml));
            asm("cvt.f32.f16 %0, %1;" : "=f"(mB) : "h"(mh));
            u64 M = pack2(mA, mB);
            float wwx = __uint_as_float(w.z);
            float wwy = __uint_as_float(w.w);
            acc0a = ffma2(M, pack2(wwx, wwx), acc0a);
            acc1a = ffma2(M, pack2(wwy, wwy), acc1a);
        }
        {
            uint4 w = sw[j + 1];
            u32 wxx = prmt(w.x, 0x1010u);
            u32 wyy = prmt(w.x, 0x3232u);
            u32 p = hfma2(Y0h, wxx, hfma2(Y1h, wyy, w.y));
            u32 th; asm("tanh.approx.f16x2 %0, %1;" : "=r"(th) : "r"(p));
            u32 m = hfma2(th, th, NEG1H);
            unsigned short ml, mh;
            asm("mov.b32 {%0, %1}, %2;" : "=h"(ml), "=h"(mh) : "r"(m));
            float mA, mB;
            asm("cvt.f32.f16 %0, %1;" : "=f"(mA) : "h"(ml));
            asm("cvt.f32.f16 %0, %1;" : "=f"(mB) : "h"(mh));
            u64 M = pack2(mA, mB);
            float wwx = __uint_as_float(w.z);
            float wwy = __uint_as_float(w.w);
            acc0b = ffma2(M, pack2(wwx, wwx), acc0b);
            acc1b = ffma2(M, pack2(wwy, wwy), acc1b);
        }
    }
    float a0A, a0B, b0A, b0B, a1A, a1B, b1A, b1B;
    unpack2(acc0a, a0A, a0B); unpack2(acc0b, b0A, b0B);
    unpack2(acc1a, a1A, a1B); unpack2(acc1b, b1A, b1B);
    gA0 = a0A + b0A;  gB0 = a0B + b0B;
    gA1 = a1A + b1A;  gB1 = a1B + b1B;
}

__global__ void __launch_bounds__(256, 4)
gyro_kernel(const float4* __restrict__ rin, float4* __restrict__ out,
            int B, int half)
{
    __shared__ uint4  sw[NLAYERS * NEUR];
    __shared__ float2 seta[NLAYERS];
    __shared__ float2 scs;

    for (int i = threadIdx.x; i < NLAYERS * NEUR; i += blockDim.x)
        sw[i] = g_w[i];
    if (threadIdx.x < NLAYERS) seta[threadIdx.x] = g_eta[threadIdx.x];
    if (threadIdx.x == 0)      scs = g_cs;
    __syncthreads();

    int idx = blockIdx.x * blockDim.x + threadIdx.x;
    if (idx >= half) return;
    int idx2 = idx + half;
    bool hasB = (idx2 < B);
    int i2 = hasB ? idx2 : idx;

    float4 zA = rin[idx];
    float4 zB = rin[i2];
    float xA0 = zA.x, xA1 = zA.y, yA0 = zA.z, yA1 = zA.w;
    float xB0 = zB.x, xB1 = zB.y, yB0 = zB.z, yB1 = zB.w;

    // ---- inverse psi layers, l = 7 .. 0 ----
    for (int l = 7; l >= 0; --l) {
        float e0 = seta[l].x, e1 = seta[l].y;
        const uint4* w = &sw[l * NEUR];
#pragma unroll 1
        for (int k = 0; k < 4; ++k) {
            float ynA0 = xA0 - e0, ynA1 = xA1 - e1;
            float ynB0 = xB0 - e0, ynB1 = xB1 - e1;
            float gA0, gA1, gB0, gB1;
            grad2x2(w, ynA0, ynA1, ynB0, ynB1, gA0, gA1, gB0, gB1);
            float nxA0 = gA0 - yA0, nxA1 = gA1 - yA1;
            float nxB0 = gB0 - yB0, nxB1 = gB1 - yB1;
            yA0 = ynA0; yA1 = ynA1; xA0 = nxA0; xA1 = nxA1;
            yB0 = ynB0; yB1 = ynB1; xB0 = nxB0; xB1 = nxB1;
        }
    }

    // ---- circle action ----
    {
        float c = scs.x, s = scs.y;
        float q1 = xA0, p1 = yA0;
        xA0 = fmaf(c, q1, s * p1);
        yA0 = fmaf(c, p1, -s * q1);
        q1 = xB0; p1 = yB0;
        xB0 = fmaf(c, q1, s * p1);
        yB0 = fmaf(c, p1, -s * q1);
    }

    // ---- forward layers: l = 0..7 psi, l = 8..15 ni ----
    for (int l = 0; l < NLAYERS; ++l) {
        float e0 = seta[l].x, e1 = seta[l].y;
        const uint4* w = &sw[l * NEUR];
#pragma unroll 1
        for (int k = 0; k < 4; ++k) {
            float gA0, gA1, gB0, gB1;
            grad2x2(w, yA0, yA1, yB0, yB1, gA0, gA1, gB0, gB1);
            float nxA0 = yA0 + e0, nxA1 = yA1 + e1;
            float nyA0 = gA0 - xA0, nyA1 = gA1 - xA1;
            float nxB0 = yB0 + e0, nxB1 = yB1 + e1;
            float nyB0 = gB0 - xB0, nyB1 = gB1 - xB1;
            xA0 = nxA0; xA1 = nxA1; yA0 = nyA0; yA1 = nyA1;
            xB0 = nxB0; xB1 = nxB1; yB0 = nyB0; yB1 = nyB1;
        }
    }

    out[idx] = make_float4(xA0, xA1, yA0, yA1);
    if (hasB)
        out[idx2] = make_float4(xB0, xB1, yB0, yB1);
}

extern "C" void kernel_launch(void* const* d_in, const int* in_sizes, int n_in,
                              void* d_out, int out_size)
{
    const float* r        = (const float*)d_in[0];
    const float* theta0   = (const float*)d_in[1];
    const float* psi_Win  = (const float*)d_in[2];
    const float* psi_Wout = (const float*)d_in[3];
    const float* psi_b    = (const float*)d_in[4];
    const float* psi_eta  = (const float*)d_in[5];
    const float* ni_Win   = (const float*)d_in[6];
    const float* ni_Wout  = (const float*)d_in[7];
    const float* ni_b     = (const float*)d_in[8];
    const float* ni_eta   = (const float*)d_in[9];

    int B = in_sizes[0] / 4;
    int half = (B + 1) / 2;

    prep_kernel<<<1, 1024>>>(theta0, psi_Win, psi_Wout, psi_b, psi_eta,
                             ni_Win, ni_Wout, ni_b, ni_eta);

    int threads = 256;
    int blocks = (half + threads - 1) / threads;
    gyro_kernel<<<blocks, threads>>>((const float4*)r, (float4*)d_out, B, half);
}